// round 8
// baseline (speedup 1.0000x reference)
#include <cuda_runtime.h>
#include <cuda_fp16.h>
#include <stdint.h>

#define BATCH 2048
#define CIN   256
#define LIN   256
#define COUT  64
#define LOUT  61
#define FLAT  3904   // permuted k' = l*64 + co
#define H1    512
#define H2    128

// ---------------- device-global scratch (allocation-free rule) ----------------
__device__ __half g_WcH[COUT * 4096];                 // BN-folded conv weights fp16
__device__ float  g_bshift[COUT];
__device__ __half g_actH[(size_t)BATCH * FLAT];       // conv output fp16, [b][l*64+co]
__device__ float  g_W12p[2][H2 * FLAT];               // split-K partials of fused weights
__device__ __half g_W12h[H2 * FLAT];                  // fused fc2@fc1 weights fp16, [n][k']
__device__ float  g_b12[H2];
__device__ float  g_part[4 * (size_t)BATCH * H2];     // split-K partials (fc)

// ---------------- helpers ----------------
__device__ __forceinline__ uint32_t packh2(float a, float b) {
    __half2 h = __floats2half2_rn(a, b);
    return *reinterpret_cast<uint32_t*>(&h);
}
__device__ __forceinline__ void mma16816(float* d, const uint32_t* a, const uint32_t* b) {
    asm volatile("mma.sync.aligned.m16n8k16.row.col.f32.f16.f16.f32 "
                 "{%0,%1,%2,%3}, {%4,%5,%6,%7}, {%8,%9}, {%0,%1,%2,%3};"
                 : "+f"(d[0]), "+f"(d[1]), "+f"(d[2]), "+f"(d[3])
                 : "r"(a[0]), "r"(a[1]), "r"(a[2]), "r"(a[3]), "r"(b[0]), "r"(b[1]));
}
__device__ __forceinline__ void ldsm4(uint32_t* r, uint32_t addr) {
    asm volatile("ldmatrix.sync.aligned.m8n8.x4.shared.b16 {%0,%1,%2,%3}, [%4];"
                 : "=r"(r[0]), "=r"(r[1]), "=r"(r[2]), "=r"(r[3]) : "r"(addr));
}
__device__ __forceinline__ void ldsm4t(uint32_t* r, uint32_t addr) {
    asm volatile("ldmatrix.sync.aligned.m8n8.x4.trans.shared.b16 {%0,%1,%2,%3}, [%4];"
                 : "=r"(r[0]), "=r"(r[1]), "=r"(r[2]), "=r"(r[3]) : "r"(addr));
}
__device__ __forceinline__ uint32_t cvta_sm(const void* p) {
    uint32_t a;
    asm("{ .reg .u64 t; cvta.to.shared.u64 t, %1; cvt.u32.u64 %0, t; }" : "=r"(a) : "l"(p));
    return a;
}

// ===========================================================================
// prep_split: fold BN into conv weights -> fp16; compute bshift.
// ===========================================================================
__global__ void prep_split(const float* __restrict__ cw, const float* __restrict__ cb,
                           const float* __restrict__ gam, const float* __restrict__ bet,
                           const float* __restrict__ mn, const float* __restrict__ vr)
{
    int gid = blockIdx.x * blockDim.x + threadIdx.x;
    int stride = gridDim.x * blockDim.x;
    for (int i = gid; i < COUT * 4096; i += stride) {
        int co = i >> 12;
        float inv = gam[co] * rsqrtf(vr[co] + 1e-5f);
        g_WcH[i] = __float2half_rn(cw[i] * inv);
    }
    if (gid < COUT) {
        float inv = gam[gid] * rsqrtf(vr[gid] + 1e-5f);
        g_bshift[gid] = (cb[gid] - mn[gid]) * inv + bet[gid];
    }
}

// ===========================================================================
// prep_b12: b12[n] = fc2_b[n] + sum_h fc2_w[n,h]*fc1_b[h].
// ===========================================================================
__global__ void prep_b12(const float* __restrict__ w2, const float* __restrict__ b1,
                         const float* __restrict__ b2)
{
    int wid = (blockIdx.x * blockDim.x + threadIdx.x) >> 5;
    int lane = threadIdx.x & 31;
    if (wid >= H2) return;
    float s = 0.0f;
    for (int h = lane; h < H1; h += 32) s += w2[wid * H1 + h] * b1[h];
#pragma unroll
    for (int o = 16; o > 0; o >>= 1) s += __shfl_xor_sync(0xFFFFFFFF, s, o);
    if (lane == 0) g_b12[wid] = b2[wid] + s;
}

// ===========================================================================
// prep_w12: W12p[ksp][n][perm(k_orig)] = sum_{h in K-half} w2[n,h]*w1[h,k_orig]
// Computed in ORIGINAL k layout (coalesced w1 rows), stores permuted.
// Grid (31 k_orig-tiles of 128, 2 K-halves of 256). 256 thr, 8 warps 32x64.
// A = w2 [n][h] via ldmatrix; B = w1 [h][k] via ldmatrix.trans.
// ===========================================================================
__global__ __launch_bounds__(256) void prep_w12(const float* __restrict__ w2,
                                                const float* __restrict__ w1)
{
    __shared__ uint32_t As[128 * 36];   // [n][h] halves: 64h = 32w + 4 pad
    __shared__ uint32_t Bs[64 * 68];    // [h][k] halves: 128k = 64w + 4 pad

    const int tid = threadIdx.x, wid = tid >> 5, lane = tid & 31;
    const int g = lane >> 2, tig = lane & 3;
    const int mw = (wid & 3) * 32;          // n-rows 32 per warp
    const int nwb = (wid >> 2) * 64;        // k-cols 64 per warp
    const int n0 = blockIdx.x * 128;        // k_orig tile base
    const int ksp = blockIdx.y;
    const int cols_valid = FLAT - n0;       // cols in this tile (>=128 except last=64)
    const uint32_t sa = cvta_sm(As), sbb = cvta_sm(Bs);

    float acc[2][8][4];
#pragma unroll
    for (int a = 0; a < 2; a++)
#pragma unroll
        for (int b = 0; b < 8; b++)
#pragma unroll
            for (int c2 = 0; c2 < 4; c2++) acc[a][b][c2] = 0.0f;

    for (int c = 0; c < 4; c++) {
        const int h0 = ksp * 256 + c * 64;
        __syncthreads();
        // A: w2 128n x 64h
#pragma unroll
        for (int i = 0; i < 8; i++) {
            int u = tid + 256 * i;
            int n = u >> 4, h4 = u & 15;
            float4 v = *(const float4*)(w2 + n * H1 + h0 + 4 * h4);
            As[n * 36 + 2 * h4]     = packh2(v.x, v.y);
            As[n * 36 + 2 * h4 + 1] = packh2(v.z, v.w);
        }
        // B: w1 64h x 128k (guard tail tile)
#pragma unroll
        for (int i = 0; i < 8; i++) {
            int u = tid + 256 * i;
            int h = u >> 5, k4 = u & 31;
            float4 v = make_float4(0.f, 0.f, 0.f, 0.f);
            if (4 * k4 + 4 <= cols_valid)
                v = *(const float4*)(w1 + (size_t)(h0 + h) * FLAT + n0 + 4 * k4);
            Bs[h * 68 + 2 * k4]     = packh2(v.x, v.y);
            Bs[h * 68 + 2 * k4 + 1] = packh2(v.z, v.w);
        }
        __syncthreads();
#pragma unroll
        for (int ks = 0; ks < 4; ks++) {
            uint32_t A[2][4], B[8][2];
#pragma unroll
            for (int mf = 0; mf < 2; mf++) {
                uint32_t addr = sa + ((mw + mf * 16 + (lane & 15)) * 36
                                      + ks * 8 + (lane >> 4) * 4) * 4;
                ldsm4(A[mf], addr);
            }
#pragma unroll
            for (int q = 0; q < 4; q++) {
                uint32_t r[4];
                uint32_t row = ks * 16 + ((lane >> 3) & 1) * 8 + (lane & 7);
                uint32_t colw = (nwb + q * 16) / 2 + (lane >> 4) * 4;
                ldsm4t(r, sbb + (row * 68 + colw) * 4);
                B[2 * q][0] = r[0]; B[2 * q][1] = r[1];
                B[2 * q + 1][0] = r[2]; B[2 * q + 1][1] = r[3];
            }
#pragma unroll
            for (int mf = 0; mf < 2; mf++)
#pragma unroll
                for (int nf = 0; nf < 8; nf++)
                    mma16816(acc[mf][nf], A[mf], B[nf]);
        }
    }
    // epilogue: scatter to permuted layout k' = l*64+co (k_orig = co*61+l)
    float* dst = g_W12p[ksp];
#pragma unroll
    for (int nf = 0; nf < 8; nf++) {
        int k0 = n0 + nwb + 8 * nf + 2 * tig;
#pragma unroll
        for (int e = 0; e < 2; e++) {
            int k = k0 + e;
            if (k < FLAT) {
                int co = k / 61, l = k - 61 * co;
                int kp = l * 64 + co;
#pragma unroll
                for (int mf = 0; mf < 2; mf++) {
                    int m = mw + 16 * mf + g;
                    dst[m * FLAT + kp]       = acc[mf][nf][e];
                    dst[(m + 8) * FLAT + kp] = acc[mf][nf][2 + e];
                }
            }
        }
    }
}

// ===========================================================================
// combine_w12: W12h = fp16(p0 + p1)
// ===========================================================================
__global__ void combine_w12()
{
    int i = blockIdx.x * blockDim.x + threadIdx.x;
    int stride = gridDim.x * blockDim.x;
    for (; i < H2 * FLAT; i += stride)
        g_W12h[i] = __float2half_rn(g_W12p[0][i] + g_W12p[1][i]);
}

// ===========================================================================
// conv_mma3: Conv1d+BN+ReLU implicit-im2col GEMM.
// CTA = 4 batches (one per warp), 128 thr. M=256, N=64, K=4096 in 64 chunks
// of 64 k (4 ci x 16 taps). Dynamic smem ping-pong (55.3 KB), 1 sync/chunk.
// x regions: 16 x 288 words (aligned copy + 8B-shifted copy) -> conflict-free
// ldmatrix for even/odd im2col rows. Weights: 64co x 36 words.
// ===========================================================================
#define CV_BSB   (16 * 288)                 // 4608 words
#define CV_BUFW  (CV_BSB + 64 * 36)         // 6912 words = 27648 B
#define CV_SMEM  (2 * CV_BUFW * 4)          // 55296 B

__global__ __launch_bounds__(128) void conv_mma3(const float* __restrict__ x)
{
    extern __shared__ uint32_t smd[];

    const int tid = threadIdx.x, wid = tid >> 5, lane = tid & 31;
    const int g = lane >> 2, tig = lane & 3;
    const int b0 = blockIdx.x * 4;
    const uint32_t smb = cvta_sm(smd);

    float acc[4][8][4];
#pragma unroll
    for (int a = 0; a < 4; a++)
#pragma unroll
        for (int b = 0; b < 8; b++)
#pragma unroll
            for (int c2 = 0; c2 < 4; c2++) acc[a][b][c2] = 0.0f;

    // x staging map: e = tid+128i, i 0..7 -> (bi, cil, t4)
    uint32_t xoff[8];
    int sA[8];
    bool doB[8];
#pragma unroll
    for (int i = 0; i < 8; i++) {
        int e = tid + 128 * i;
        int bi = e >> 8, cil = (e >> 6) & 3, t4 = e & 63;
        xoff[i] = (uint32_t)(b0 + bi) * 65536u + cil * 256 + 4 * t4;
        sA[i] = (bi * 4 + cil) * 288 + 2 * t4;
        doB[i] = (t4 >= 1);
    }
    // weight staging map: u = tid+128i, i 0..3 -> (co, q)
    int woff[4], bso[4];
#pragma unroll
    for (int i = 0; i < 4; i++) {
        int u = tid + 128 * i;
        int co = u >> 3, q = u & 7;
        woff[i] = co * 4096 + q * 8;
        bso[i] = CV_BSB + co * 36 + q * 4;
    }
    // ldmatrix A offset within region (verified layout from R7)
    const uint32_t aoff = (lane & 1) * 576 + (((lane & 15) >> 1) + (lane >> 4)) * 16;
    // ldmatrix B word offset
    const int nbt = 8 * (lane >> 4) + (lane & 7);
    const uint32_t boffw = (uint32_t)(CV_BSB + nbt * 36 + ((lane >> 3) & 1) * 4);

    float4 xv[8];
    uint4  wv[4];

#define LDGX(cc) do { \
    _Pragma("unroll") for (int i = 0; i < 8; i++) \
        xv[i] = *(const float4*)(x + xoff[i] + (uint32_t)(cc) * 1024u); \
    _Pragma("unroll") for (int i = 0; i < 4; i++) \
        wv[i] = *(const uint4*)(g_WcH + woff[i] + (cc) * 64); \
} while (0)

#define STSX(bf) do { \
    uint32_t* B_ = smd + (bf) * CV_BUFW; \
    _Pragma("unroll") for (int i = 0; i < 8; i++) { \
        uint32_t h0 = packh2(xv[i].x, xv[i].y); \
        uint32_t h1 = packh2(xv[i].z, xv[i].w); \
        *(uint2*)&B_[sA[i]] = make_uint2(h0, h1); \
        if (doB[i]) *(uint2*)&B_[sA[i] + 142] = make_uint2(h0, h1); \
    } \
    _Pragma("unroll") for (int i = 0; i < 4; i++) \
        *(uint4*)&B_[bso[i]] = wv[i]; \
} while (0)

    LDGX(0);
    STSX(0);
    LDGX(1);
    __syncthreads();

#pragma unroll 1
    for (int c = 0; c < 64; c++) {
        const int buf = c & 1;
        if (c < 63) STSX(buf ^ 1);
        if (c < 62) LDGX(c + 2);

        const uint32_t bb = smb + buf * (CV_BUFW * 4);
#pragma unroll
        for (int ks = 0; ks < 4; ks++) {
            uint32_t A[4][4], B[8][2];
            const uint32_t abase = bb + (uint32_t)((wid * 4 + ks) * 1152) + aoff;
#pragma unroll
            for (int mf = 0; mf < 4; mf++) ldsm4(A[mf], abase + mf * 128);
            const uint32_t bbase = bb + (boffw + ks * 8) * 4;
#pragma unroll
            for (int q = 0; q < 4; q++) {
                uint32_t r[4];
                ldsm4(r, bbase + (uint32_t)(16 * q * 36) * 4);
                B[2 * q][0] = r[0]; B[2 * q][1] = r[1];
                B[2 * q + 1][0] = r[2]; B[2 * q + 1][1] = r[3];
            }
#pragma unroll
            for (int mf = 0; mf < 4; mf++)
#pragma unroll
                for (int nf = 0; nf < 8; nf++)
                    mma16816(acc[mf][nf], A[mf], B[nf]);
        }
        __syncthreads();
    }

    // epilogue: warp = batch b0+wid
    const size_t obase = (size_t)(b0 + wid) * FLAT;
#pragma unroll
    for (int nf = 0; nf < 8; nf++) {
        int co = 8 * nf + 2 * tig;
        float s0 = g_bshift[co], s1 = g_bshift[co + 1];
#pragma unroll
        for (int mf = 0; mf < 4; mf++) {
            int lp0 = 16 * mf + g;
            if (lp0 < 61)
                *(uint32_t*)(g_actH + obase + lp0 * 64 + co) =
                    packh2(fmaxf(acc[mf][nf][0] + s0, 0.0f),
                           fmaxf(acc[mf][nf][1] + s1, 0.0f));
            int lp1 = lp0 + 8;
            if (lp1 < 61)
                *(uint32_t*)(g_actH + obase + lp1 * 64 + co) =
                    packh2(fmaxf(acc[mf][nf][2] + s0, 0.0f),
                           fmaxf(acc[mf][nf][3] + s1, 0.0f));
        }
    }
#undef LDGX
#undef STSX
}

// ===========================================================================
// fc_part: split-K fused FC. part[ks][b][n] = act[b,:] . W12[n,:] (K slice)
// ===========================================================================
__global__ __launch_bounds__(256, 2) void fc_part()
{
    __shared__ uint32_t As[128 * 36];
    __shared__ uint32_t Bs[128 * 36];

    const int tid = threadIdx.x, wid = tid >> 5, lane = tid & 31;
    const int g = lane >> 2, tig = lane & 3;
    const int mbase = (wid >> 1) * 32, nbase = (wid & 1) * 64;
    const int m0 = blockIdx.x * 128;
    const int ksp = blockIdx.y;
    const int cb = (61 * ksp) / 4, ce = (61 * (ksp + 1)) / 4;

    float acc[2][8][4];
#pragma unroll
    for (int a = 0; a < 2; a++)
#pragma unroll
        for (int b = 0; b < 8; b++)
#pragma unroll
            for (int c2 = 0; c2 < 4; c2++) acc[a][b][c2] = 0.0f;

    for (int c = cb; c < ce; c++) {
        __syncthreads();
#pragma unroll
        for (int i = 0; i < 4; i++) {
            int u = tid + 256 * i;
            int row = u >> 3, q = u & 7;
            uint4 av = *(const uint4*)(g_actH + (size_t)(m0 + row) * FLAT + c * 64 + q * 8);
            uint4 bv = *(const uint4*)(g_W12h + (size_t)row * FLAT + c * 64 + q * 8);
            *(uint4*)&As[row * 36 + q * 4] = av;
            *(uint4*)&Bs[row * 36 + q * 4] = bv;
        }
        __syncthreads();
#pragma unroll
        for (int ks = 0; ks < 4; ks++) {
            uint32_t A[2][4], B[8][2];
#pragma unroll
            for (int mf = 0; mf < 2; mf++) {
                int r = mbase + 16 * mf + g;
                int wd = r * 36 + ks * 8 + tig;
                A[mf][0] = As[wd];       A[mf][1] = As[wd + 8 * 36];
                A[mf][2] = As[wd + 4];   A[mf][3] = As[wd + 8 * 36 + 4];
            }
#pragma unroll
            for (int nf = 0; nf < 8; nf++) {
                int n = nbase + 8 * nf + g;
                int wd = n * 36 + ks * 8 + tig;
                B[nf][0] = Bs[wd]; B[nf][1] = Bs[wd + 4];
            }
#pragma unroll
            for (int mf = 0; mf < 2; mf++)
#pragma unroll
                for (int nf = 0; nf < 8; nf++)
                    mma16816(acc[mf][nf], A[mf], B[nf]);
        }
    }
#pragma unroll
    for (int nf = 0; nf < 8; nf++) {
        int c0 = nbase + 8 * nf + 2 * tig;
#pragma unroll
        for (int mf = 0; mf < 2; mf++) {
            int r = mbase + 16 * mf + g;
            *(float2*)(g_part + ((size_t)ksp * BATCH + m0 + r) * H2 + c0) =
                make_float2(acc[mf][nf][0], acc[mf][nf][1]);
            *(float2*)(g_part + ((size_t)ksp * BATCH + m0 + r + 8) * H2 + c0) =
                make_float2(acc[mf][nf][2], acc[mf][nf][3]);
        }
    }
}

// ===========================================================================
// fc_reduce: sum split-K partials + b12, apply parabit heads.
// ===========================================================================
__global__ void fc_reduce(const float* __restrict__ bw, const float* __restrict__ bb,
                          float* __restrict__ out)
{
    int idx = blockIdx.x * blockDim.x + threadIdx.x;
    int n = idx & 127;
    float s = g_b12[n];
#pragma unroll
    for (int ks = 0; ks < 4; ks++)
        s += g_part[(size_t)ks * BATCH * H2 + idx];
    float2 o = make_float2(fmaf(s, bw[2 * n], bb[2 * n]),
                           fmaf(s, bw[2 * n + 1], bb[2 * n + 1]));
    *(float2*)(out + (size_t)idx * 2) = o;
}

// ===========================================================================
extern "C" void kernel_launch(void* const* d_in, const int* in_sizes, int n_in,
                              void* d_out, int out_size)
{
    const float* x      = (const float*)d_in[0];
    const float* conv_w = (const float*)d_in[1];
    const float* conv_b = (const float*)d_in[2];
    const float* bn_g   = (const float*)d_in[3];
    const float* bn_b   = (const float*)d_in[4];
    const float* bn_m   = (const float*)d_in[5];
    const float* bn_v   = (const float*)d_in[6];
    const float* fc1_w  = (const float*)d_in[7];
    const float* fc1_b  = (const float*)d_in[8];
    const float* fc2_w  = (const float*)d_in[9];
    const float* fc2_b  = (const float*)d_in[10];
    const float* bit_w  = (const float*)d_in[11];
    const float* bit_b  = (const float*)d_in[12];
    float* out = (float*)d_out;

    cudaFuncSetAttribute(conv_mma3, cudaFuncAttributeMaxDynamicSharedMemorySize, CV_SMEM);

    prep_split<<<256, 256>>>(conv_w, conv_b, bn_g, bn_b, bn_m, bn_v);
    prep_b12<<<16, 256>>>(fc2_w, fc1_b, fc2_b);
    prep_w12<<<dim3(31, 2), 256>>>(fc2_w, fc1_w);
    combine_w12<<<488, 256>>>();
    conv_mma3<<<BATCH / 4, 128, CV_SMEM>>>(x);
    fc_part<<<dim3(16, 4), 256>>>();
    fc_reduce<<<BATCH * H2 / 256, 256>>>(bit_w, bit_b, out);
}